// round 2
// baseline (speedup 1.0000x reference)
#include <cuda_runtime.h>
#include <math.h>

#define SEQ 2048
#define DIM 2048
#define NH 32
#define NKVH 8
#define HD 64
#define QSTRIDE (NH*HD)     // 2048
#define KSTRIDE (NKVH*HD)   // 512

// scratch (device globals: no allocation allowed)
__device__ float g_q[SEQ * QSTRIDE];
__device__ float g_k[SEQ * KSTRIDE];
__device__ float g_v[SEQ * KSTRIDE];
__device__ float g_ao[SEQ * QSTRIDE];

// ---------------------------------------------------------------------------
// SGEMM core: C[m, n] = sum_k X[m*K+k] * W[n*K+k] + bias[n]
// 128x128 tile, BK=8, 256 threads, 8x8 per-thread microtile, reg prefetch.
// Caller pre-offsets W/bias/C so this tile's n range starts at 0.
// ---------------------------------------------------------------------------
struct GemmSmem {
    float As[8][128];
    float Bs[8][128];
};

__device__ __forceinline__ void gemm_tile_128(
    const float* __restrict__ X, const float* __restrict__ Wblk,
    const float* __restrict__ biasblk, float* __restrict__ Cblk,
    int ldc, int m0, int K, GemmSmem& sm)
{
    const int tid = threadIdx.x;
    const int tx = tid & 15;        // 0..15 -> n microtile
    const int ty = tid >> 4;        // 0..15 -> m microtile
    const int lr = tid >> 1;        // load row 0..127
    const int lk = (tid & 1) * 4;   // load k offset 0 or 4

    const float* Aptr = X + (size_t)(m0 + lr) * K + lk;
    const float* Bptr = Wblk + (size_t)lr * K + lk;

    float4 a_pf = *(const float4*)Aptr;
    float4 b_pf = *(const float4*)Bptr;

    float acc[8][8];
    #pragma unroll
    for (int i = 0; i < 8; i++)
        #pragma unroll
        for (int j = 0; j < 8; j++) acc[i][j] = 0.f;

    const int nt = K >> 3;
    for (int kt = 0; kt < nt; kt++) {
        sm.As[lk + 0][lr] = a_pf.x;
        sm.As[lk + 1][lr] = a_pf.y;
        sm.As[lk + 2][lr] = a_pf.z;
        sm.As[lk + 3][lr] = a_pf.w;
        sm.Bs[lk + 0][lr] = b_pf.x;
        sm.Bs[lk + 1][lr] = b_pf.y;
        sm.Bs[lk + 2][lr] = b_pf.z;
        sm.Bs[lk + 3][lr] = b_pf.w;
        __syncthreads();

        if (kt + 1 < nt) {
            a_pf = *(const float4*)(Aptr + (kt + 1) * 8);
            b_pf = *(const float4*)(Bptr + (kt + 1) * 8);
        }

        #pragma unroll
        for (int kk = 0; kk < 8; kk++) {
            float af[8], bf[8];
            *(float4*)(af + 0) = *(const float4*)&sm.As[kk][ty * 8 + 0];
            *(float4*)(af + 4) = *(const float4*)&sm.As[kk][ty * 8 + 4];
            *(float4*)(bf + 0) = *(const float4*)&sm.Bs[kk][tx * 8 + 0];
            *(float4*)(bf + 4) = *(const float4*)&sm.Bs[kk][tx * 8 + 4];
            #pragma unroll
            for (int i = 0; i < 8; i++)
                #pragma unroll
                for (int j = 0; j < 8; j++)
                    acc[i][j] = fmaf(af[i], bf[j], acc[i][j]);
        }
        __syncthreads();
    }

    // epilogue: add bias, vector store
    float bv[8];
    #pragma unroll
    for (int j = 0; j < 8; j++) bv[j] = biasblk[tx * 8 + j];

    #pragma unroll
    for (int i = 0; i < 8; i++) {
        float* crow = Cblk + (size_t)(m0 + ty * 8 + i) * ldc + tx * 8;
        float4 o0, o1;
        o0.x = acc[i][0] + bv[0]; o0.y = acc[i][1] + bv[1];
        o0.z = acc[i][2] + bv[2]; o0.w = acc[i][3] + bv[3];
        o1.x = acc[i][4] + bv[4]; o1.y = acc[i][5] + bv[5];
        o1.z = acc[i][6] + bv[6]; o1.w = acc[i][7] + bv[7];
        *(float4*)(crow + 0) = o0;
        *(float4*)(crow + 4) = o1;
    }
}

// ---------------------------------------------------------------------------
// Fused QKV projection. grid = (24, 16): n-blocks 0..15 -> Q, 16..19 -> K,
// 20..23 -> V. m-blocks cover 2048 rows.
// ---------------------------------------------------------------------------
__global__ void __launch_bounds__(256) qkv_gemm_kernel(
    const float* __restrict__ x,
    const float* __restrict__ wq, const float* __restrict__ bq,
    const float* __restrict__ wk, const float* __restrict__ bk,
    const float* __restrict__ wv, const float* __restrict__ bv)
{
    __shared__ GemmSmem sm;
    const int nb = blockIdx.x;
    const int m0 = blockIdx.y * 128;
    if (nb < 16) {
        const int off = nb * 128;
        gemm_tile_128(x, wq + (size_t)off * DIM, bq + off, g_q + off,
                      QSTRIDE, m0, DIM, sm);
    } else if (nb < 20) {
        const int off = (nb - 16) * 128;
        gemm_tile_128(x, wk + (size_t)off * DIM, bk + off, g_k + off,
                      KSTRIDE, m0, DIM, sm);
    } else {
        const int off = (nb - 20) * 128;
        gemm_tile_128(x, wv + (size_t)off * DIM, bv + off, g_v + off,
                      KSTRIDE, m0, DIM, sm);
    }
}

// ---------------------------------------------------------------------------
// Output projection: out = g_ao @ wo^T + bo.  grid = (16, 16)
// ---------------------------------------------------------------------------
__global__ void __launch_bounds__(256) out_gemm_kernel(
    const float* __restrict__ wo, const float* __restrict__ bo,
    float* __restrict__ out)
{
    __shared__ GemmSmem sm;
    const int off = blockIdx.x * 128;
    gemm_tile_128(g_ao, wo + (size_t)off * DIM, bo + off, out + off,
                  DIM, blockIdx.y * 128, DIM, sm);
}

// ---------------------------------------------------------------------------
// RoPE (in place). One thread per (s, head, d<32) pair.
// rope_cache row: [cos(0..63) | sin(0..63)], cos[d]==cos[d+32].
// ---------------------------------------------------------------------------
__global__ void rope_kernel(const float* __restrict__ rope, int is_q)
{
    float* buf = is_q ? g_q : g_k;
    const int nh = is_q ? NH : NKVH;
    const int total = SEQ * nh * 32;
    int idx = blockIdx.x * blockDim.x + threadIdx.x;
    if (idx >= total) return;
    const int d = idx & 31;
    const int h = (idx >> 5) % nh;
    const int s = idx / (32 * nh);
    const float c  = rope[s * 128 + d];
    const float sn = rope[s * 128 + 64 + d];
    float* row = buf + (size_t)s * (nh * HD) + h * HD;
    const float x0 = row[d];
    const float x1 = row[d + 32];
    row[d]      = x0 * c - x1 * sn;
    row[d + 32] = x1 * c + x0 * sn;
}

// ---------------------------------------------------------------------------
// Causal flash attention + sink renorm.
// grid = (SEQ/128, NH), 128 threads. One q row per thread.
// ---------------------------------------------------------------------------
__global__ void __launch_bounds__(128) flash_kernel(
    const float* __restrict__ sinks)
{
    __shared__ float Ks[64][64];
    __shared__ float Vs[64][64];

    const int h   = blockIdx.y;
    const int kvh = h >> 2;               // REP = 4
    const int q0  = blockIdx.x * 128;
    const int tid = threadIdx.x;
    const int sq  = q0 + tid;
    const float scale = 0.125f;           // 1/sqrt(64)

    float qreg[64];
    {
        const float* qrow = g_q + (size_t)sq * QSTRIDE + h * HD;
        #pragma unroll
        for (int d4 = 0; d4 < 16; d4++) {
            float4 qv = *(const float4*)(qrow + d4 * 4);
            qreg[d4 * 4 + 0] = qv.x * scale;
            qreg[d4 * 4 + 1] = qv.y * scale;
            qreg[d4 * 4 + 2] = qv.z * scale;
            qreg[d4 * 4 + 3] = qv.w * scale;
        }
    }

    float acc[64];
    #pragma unroll
    for (int d = 0; d < 64; d++) acc[d] = 0.f;
    float m = -INFINITY;
    float l = 0.f;

    const int nt = blockIdx.x * 2 + 2;    // kv tiles of 64 covering [0, q0+128)
    for (int t = 0; t < nt; t++) {
        const int base = t * 64;
        // cooperative K/V tile load (float4, coalesced)
        #pragma unroll
        for (int i = 0; i < 8; i++) {
            const int lin = tid + i * 128;      // 0..1023 float4 slots
            const int r  = lin >> 4;
            const int c4 = (lin & 15) << 2;
            const size_t goff = (size_t)(base + r) * KSTRIDE + kvh * HD + c4;
            *(float4*)&Ks[r][c4] = *(const float4*)(g_k + goff);
            *(float4*)&Vs[r][c4] = *(const float4*)(g_v + goff);
        }
        __syncthreads();

        for (int kk = 0; kk < 64; kk++) {
            if (base + kk > sq) break;          // causal (divergent break ok)
            float sc = 0.f;
            #pragma unroll
            for (int d4 = 0; d4 < 16; d4++) {
                const float4 kf = *(const float4*)&Ks[kk][d4 * 4];
                sc = fmaf(qreg[d4 * 4 + 0], kf.x, sc);
                sc = fmaf(qreg[d4 * 4 + 1], kf.y, sc);
                sc = fmaf(qreg[d4 * 4 + 2], kf.z, sc);
                sc = fmaf(qreg[d4 * 4 + 3], kf.w, sc);
            }
            if (sc > m) {                       // lazy rescale
                const float corr = __expf(m - sc);
                l *= corr;
                #pragma unroll
                for (int d = 0; d < 64; d++) acc[d] *= corr;
                m = sc;
            }
            const float p = __expf(sc - m);
            l += p;
            #pragma unroll
            for (int d4 = 0; d4 < 16; d4++) {
                const float4 vf = *(const float4*)&Vs[kk][d4 * 4];
                acc[d4 * 4 + 0] = fmaf(p, vf.x, acc[d4 * 4 + 0]);
                acc[d4 * 4 + 1] = fmaf(p, vf.y, acc[d4 * 4 + 1]);
                acc[d4 * 4 + 2] = fmaf(p, vf.z, acc[d4 * 4 + 2]);
                acc[d4 * 4 + 3] = fmaf(p, vf.w, acc[d4 * 4 + 3]);
            }
        }
        __syncthreads();
    }

    // sink-token LSE renormalization
    const float lse = m + __logf(l);
    const float sk  = sinks[h];
    const float dmax = fmaxf(lse, sk);
    const float combined = dmax + log1pf(__expf(-fabsf(lse - sk)));
    const float r = __expf(fmaxf(lse - combined, -20.f));
    const float inv = r / l;

    float* orow = g_ao + (size_t)sq * QSTRIDE + h * HD;
    #pragma unroll
    for (int d4 = 0; d4 < 16; d4++) {
        float4 o;
        o.x = acc[d4 * 4 + 0] * inv;
        o.y = acc[d4 * 4 + 1] * inv;
        o.z = acc[d4 * 4 + 2] * inv;
        o.w = acc[d4 * 4 + 3] * inv;
        *(float4*)(orow + d4 * 4) = o;
    }
}

// ---------------------------------------------------------------------------
extern "C" void kernel_launch(void* const* d_in, const int* in_sizes, int n_in,
                              void* d_out, int out_size)
{
    const float* x     = (const float*)d_in[0];
    const float* rope  = (const float*)d_in[1];
    const float* wq    = (const float*)d_in[2];
    const float* bq    = (const float*)d_in[3];
    const float* wk    = (const float*)d_in[4];
    const float* bk    = (const float*)d_in[5];
    const float* wv    = (const float*)d_in[6];
    const float* bv    = (const float*)d_in[7];
    const float* wo    = (const float*)d_in[8];
    const float* bo    = (const float*)d_in[9];
    const float* sinks = (const float*)d_in[10];
    float* out = (float*)d_out;

    // 1) fused QKV projection
    qkv_gemm_kernel<<<dim3(24, 16), 256>>>(x, wq, bq, wk, bk, wv, bv);

    // 2) RoPE on q and k
    {
        const int tq = SEQ * NH * 32;
        rope_kernel<<<(tq + 255) / 256, 256>>>(rope, 1);
        const int tk = SEQ * NKVH * 32;
        rope_kernel<<<(tk + 255) / 256, 256>>>(rope, 0);
    }

    // 3) causal flash attention + sink renorm
    flash_kernel<<<dim3(SEQ / 128, NH), 128>>>(sinks);

    // 4) output projection
    out_gemm_kernel<<<dim3(16, 16), 256>>>(wo, bo, out);
}